// round 13
// baseline (speedup 1.0000x reference)
#include <cuda_runtime.h>
#include <cstdint>

#define MAX_N 100000
#define MAX_E 2000000
#define F 128

// ---------------- device scratch (no allocations allowed) ----------------
__device__ int   g_cnt[MAX_N];             // in-degree (int)
__device__ int   g_off[MAX_N];             // CSR offsets
__device__ int   g_cur[MAX_N];             // fill cursors
__device__ int   g_bsum[1024];             // block sums for scan
__device__ float g_dis[MAX_N];             // deg_inv_sqrt
__device__ int2  g_epack[MAX_E];           // (src, norm bits) grouped by dst
__device__ float g_h  [(size_t)MAX_N * F]; // GEMM output (per layer)
__device__ float g_x2 [(size_t)MAX_N * F]; // layer-1 activation
__device__ int   g_is64;                   // 1 if edge_index is int64

// ---------------- helpers ----------------
__device__ __forceinline__ int load_idx(const void* ei, long long pos) {
    if (g_is64) return (int)((const long long*)ei)[pos];
    return ((const int*)ei)[pos];
}

// ---------------- fused zero + dtype sniff ----------------
__global__ void zero_detect_kernel(const void* ei, int n) {
    int i = blockIdx.x * blockDim.x + threadIdx.x;
    if (i < n) g_cnt[i] = 0;
    if (i == 0) {
        const int* w = (const int*)ei;
        int all_zero = 1;
        // values in [0, 100000): int64 hi-words are 0; false-positive ~0.
        for (int j = 1; j < 64; j += 2) all_zero &= (w[j] == 0);
        g_is64 = all_zero;
    }
}

// ---------------- degree accumulation (dst side, int) ----------------
__global__ void deg_kernel(const void* __restrict__ ei, int E) {
    int i = blockIdx.x * blockDim.x + threadIdx.x;
    if (i >= E) return;
    atomicAdd(&g_cnt[load_idx(ei, (long long)E + i)], 1);
}

// ---------------- scan1 fused with deg_inv_sqrt ----------------
__global__ void scan1_dis_kernel(int n) {
    __shared__ int sm[256];
    int t = threadIdx.x;
    int i = blockIdx.x * 256 + t;
    int v = (i < n) ? g_cnt[i] : 0;
    if (i < n) g_dis[i] = rsqrtf((float)v + 1.0f);
    sm[t] = v;
    __syncthreads();
    for (int off = 128; off > 0; off >>= 1) {
        if (t < off) sm[t] += sm[t + off];
        __syncthreads();
    }
    if (t == 0) g_bsum[blockIdx.x] = sm[0];
}

__global__ void scan2_kernel(int nb) {
    __shared__ int sm[1024];
    int t = threadIdx.x;
    int v = (t < nb) ? g_bsum[t] : 0;
    sm[t] = v;
    __syncthreads();
    for (int off = 1; off < 1024; off <<= 1) {
        int add = (t >= off) ? sm[t - off] : 0;
        __syncthreads();
        sm[t] += add;
        __syncthreads();
    }
    if (t < nb) g_bsum[t] = sm[t] - v;   // exclusive
}

__global__ void scan3_kernel(int n) {
    __shared__ int sm[256];
    int t = threadIdx.x;
    int i = blockIdx.x * 256 + t;
    int v = (i < n) ? g_cnt[i] : 0;
    sm[t] = v;
    __syncthreads();
    for (int off = 1; off < 256; off <<= 1) {
        int add = (t >= off) ? sm[t - off] : 0;
        __syncthreads();
        sm[t] += add;
        __syncthreads();
    }
    if (i < n) {
        int o = g_bsum[blockIdx.x] + sm[t] - v;   // exclusive
        g_off[i] = o;
        g_cur[i] = o;
    }
}

__global__ void fill_kernel(const void* __restrict__ ei, int E) {
    int i = blockIdx.x * blockDim.x + threadIdx.x;
    if (i >= E) return;
    int s = load_idx(ei, i);
    int d = load_idx(ei, (long long)E + i);
    float norm = g_dis[s] * g_dis[d];
    int pos = atomicAdd(&g_cur[d], 1);
    g_epack[pos] = make_int2(s, __float_as_int(norm));
}

// ---------------- GEMM: O[M,128] = X[M,128] @ W[128,128]^T ----------------
// R12 fix of the R11 redesign: SW_LD must be a multiple of 4 so the float4
// LDS stays 16B-aligned (129 trapped with misaligned address). SW_LD=132:
// aligned, load-conflict-free (proven R5/R11). Design kept from R11:
//  - no sX (x rows are all-lane-broadcast loads; smem staging bought nothing)
//  - smem 67.6 KB -> 3 CTAs/SM (24 warps vs 16)
//  - w-tile (16 regs) per kk step, xv loaded per row
#define GEMM_TM 64
#define SW_LD 132
__global__ __launch_bounds__(256, 3)
void gemm_kernel(const float* __restrict__ X, const float* __restrict__ W,
                 float* __restrict__ O, int M) {
    extern __shared__ float smem[];
    float* sW = smem;                 // [128][SW_LD] (W transposed)

    int t = threadIdx.x;
    int row0 = blockIdx.x * GEMM_TM;

    // load W transposed into shared (coalesced global reads)
    for (int idx = t; idx < 128 * 128; idx += 256) {
        int j = idx >> 7, k = idx & 127;
        sW[k * SW_LD + j] = W[idx];
    }
    __syncthreads();

    int tx = t & 31, ty = t >> 5;
    int j0 = tx * 4;

    // clamped row offsets (in float4 units); clamped rows are never stored
    int rbase[8];
    #pragma unroll
    for (int rr = 0; rr < 8; rr++) {
        int r = row0 + ty * 8 + rr;
        if (r >= M) r = M - 1;
        rbase[rr] = r * 32;
    }
    const float4* X4 = (const float4*)X;

    float acc[8][4];
    #pragma unroll
    for (int rr = 0; rr < 8; rr++)
        #pragma unroll
        for (int c = 0; c < 4; c++) acc[rr][c] = 0.f;

    #pragma unroll 4
    for (int kk = 0; kk < 128; kk += 4) {
        int k4 = kk >> 2;
        // w tile for this kk: 4 float4 (16 regs), aligned + conflict-free LDS
        float4 w0 = *(const float4*)&sW[(kk + 0) * SW_LD + j0];
        float4 w1 = *(const float4*)&sW[(kk + 1) * SW_LD + j0];
        float4 w2 = *(const float4*)&sW[(kk + 2) * SW_LD + j0];
        float4 w3 = *(const float4*)&sW[(kk + 3) * SW_LD + j0];
        #pragma unroll
        for (int rr = 0; rr < 8; rr++) {
            float4 xv = X4[rbase[rr] + k4];   // warp-broadcast global load
            acc[rr][0] += xv.x * w0.x + xv.y * w1.x + xv.z * w2.x + xv.w * w3.x;
            acc[rr][1] += xv.x * w0.y + xv.y * w1.y + xv.z * w2.y + xv.w * w3.y;
            acc[rr][2] += xv.x * w0.z + xv.y * w1.z + xv.z * w2.z + xv.w * w3.z;
            acc[rr][3] += xv.x * w0.w + xv.y * w1.w + xv.z * w2.w + xv.w * w3.w;
        }
    }

    #pragma unroll
    for (int rr = 0; rr < 8; rr++) {
        int gr = row0 + ty * 8 + rr;
        if (gr < M)
            *(float4*)&O[(size_t)gr * 128 + j0] =
                make_float4(acc[rr][0], acc[rr][1], acc[rr][2], acc[rr][3]);
    }
}

// ---------------- fused gather-aggregate + self-loop + bias + leaky ------
// One warp per dst node (proven R5 version: 2-edge unroll).
__global__ __launch_bounds__(256)
void agg_kernel(const float* __restrict__ h, const float* __restrict__ b,
                float* __restrict__ out, int n) {
    int w    = (blockIdx.x * blockDim.x + threadIdx.x) >> 5;
    int lane = threadIdx.x & 31;
    if (w >= n) return;

    int beg = g_off[w];
    int cnt = g_cnt[w];
    const float4* h4 = (const float4*)h;

    float4 acc = make_float4(0.f, 0.f, 0.f, 0.f);

    int e = 0;
    for (; e + 2 <= cnt; e += 2) {
        int2 p0 = g_epack[beg + e];
        int2 p1 = g_epack[beg + e + 1];
        float n0 = __int_as_float(p0.y);
        float n1 = __int_as_float(p1.y);
        float4 v0 = h4[(size_t)p0.x * 32 + lane];
        float4 v1 = h4[(size_t)p1.x * 32 + lane];
        acc.x += v0.x * n0 + v1.x * n1;
        acc.y += v0.y * n0 + v1.y * n1;
        acc.z += v0.z * n0 + v1.z * n1;
        acc.w += v0.w * n0 + v1.w * n1;
    }
    if (e < cnt) {
        int2 p0 = g_epack[beg + e];
        float n0 = __int_as_float(p0.y);
        float4 v0 = h4[(size_t)p0.x * 32 + lane];
        acc.x += v0.x * n0;
        acc.y += v0.y * n0;
        acc.z += v0.z * n0;
        acc.w += v0.w * n0;
    }

    float dis = g_dis[w];
    float sw  = dis * dis;
    float4 hs = h4[(size_t)w * 32 + lane];
    float4 bb = ((const float4*)b)[lane];
    acc.x += hs.x * sw + bb.x;
    acc.y += hs.y * sw + bb.y;
    acc.z += hs.z * sw + bb.z;
    acc.w += hs.w * sw + bb.w;

    acc.x = (acc.x > 0.f) ? acc.x : 0.01f * acc.x;
    acc.y = (acc.y > 0.f) ? acc.y : 0.01f * acc.y;
    acc.z = (acc.z > 0.f) ? acc.z : 0.01f * acc.z;
    acc.w = (acc.w > 0.f) ? acc.w : 0.01f * acc.w;

    ((float4*)out)[(size_t)w * 32 + lane] = acc;
}

// ---------------- launch ----------------
extern "C" void kernel_launch(void* const* d_in, const int* in_sizes, int n_in,
                              void* d_out, int out_size) {
    const float* x  = (const float*)d_in[0];
    const void*  ei = d_in[1];
    const float* W1 = (const float*)d_in[2];
    const float* b1 = (const float*)d_in[3];
    const float* W2 = (const float*)d_in[4];
    const float* b2 = (const float*)d_in[5];
    float* out = (float*)d_out;

    int n = in_sizes[0] / F;
    int E = in_sizes[1] / 2;

    void *hp_v, *x2p_v;
    cudaGetSymbolAddress(&hp_v,  g_h);
    cudaGetSymbolAddress(&x2p_v, g_x2);
    float* hp  = (float*)hp_v;
    float* x2p = (float*)x2p_v;

    const int gemm_smem = 128 * SW_LD * (int)sizeof(float);   // 67584 B
    cudaFuncSetAttribute(gemm_kernel,
                         cudaFuncAttributeMaxDynamicSharedMemorySize, gemm_smem);

    int nb        = (n + 255) / 256;
    int gemm_grid = (n + GEMM_TM - 1) / GEMM_TM;
    int node_grid = (n + 255) / 256;
    int edge_grid = (E + 255) / 256;
    int agg_grid  = ((long long)n * 32 + 255) / 256;

    // gemm1 has no CSR dependency; kept as the 4th launch so ncu's window
    // profiles it again next round (verifies occ/fma delta).
    zero_detect_kernel<<<node_grid, 256>>>(ei, n);       // 1
    deg_kernel<<<edge_grid, 256>>>(ei, E);               // 2
    scan1_dis_kernel<<<nb, 256>>>(n);                    // 3
    gemm_kernel<<<gemm_grid, 256, gemm_smem>>>(x, W1, hp, n);   // 4 <- profiled
    scan2_kernel<<<1, 1024>>>(nb);                       // 5
    scan3_kernel<<<nb, 256>>>(n);                        // 6
    fill_kernel<<<edge_grid, 256>>>(ei, E);              // 7

    // layer 1 aggregation (needs gemm1 + CSR)
    agg_kernel<<<agg_grid, 256>>>(hp, b1, x2p, n);

    // layer 2
    gemm_kernel<<<gemm_grid, 256, gemm_smem>>>(x2p, W2, hp, n);
    agg_kernel<<<agg_grid, 256>>>(hp, b2, out, n);
}

// round 14
// speedup vs baseline: 1.2369x; 1.2369x over previous
#include <cuda_runtime.h>
#include <cstdint>

#define MAX_N 100000
#define MAX_E 2000000
#define F 128

// ---------------- device scratch (no allocations allowed) ----------------
__device__ int   g_cnt[MAX_N];             // in-degree (int)
__device__ int   g_off[MAX_N];             // CSR offsets
__device__ int   g_cur[MAX_N];             // fill cursors
__device__ int   g_bsum[1024];             // block sums for scan
__device__ float g_dis[MAX_N];             // deg_inv_sqrt
__device__ int2  g_epack[MAX_E];           // (src, norm bits) grouped by dst
__device__ float g_h  [(size_t)MAX_N * F]; // GEMM output (per layer)
__device__ float g_x2 [(size_t)MAX_N * F]; // layer-1 activation
__device__ int   g_is64;                   // 1 if edge_index is int64

// ---------------- helpers ----------------
__device__ __forceinline__ int load_idx(const void* ei, long long pos) {
    if (g_is64) return (int)((const long long*)ei)[pos];
    return ((const int*)ei)[pos];
}

// ---------------- fused zero + dtype sniff ----------------
__global__ void zero_detect_kernel(const void* ei, int n) {
    int i = blockIdx.x * blockDim.x + threadIdx.x;
    if (i < n) g_cnt[i] = 0;
    if (i == 0) {
        const int* w = (const int*)ei;
        int all_zero = 1;
        // values in [0, 100000): int64 hi-words are 0; false-positive ~0.
        for (int j = 1; j < 64; j += 2) all_zero &= (w[j] == 0);
        g_is64 = all_zero;
    }
}

// ---------------- degree accumulation (dst side, int) ----------------
__global__ void deg_kernel(const void* __restrict__ ei, int E) {
    int i = blockIdx.x * blockDim.x + threadIdx.x;
    if (i >= E) return;
    atomicAdd(&g_cnt[load_idx(ei, (long long)E + i)], 1);
}

// ---------------- scan1 fused with deg_inv_sqrt ----------------
__global__ void scan1_dis_kernel(int n) {
    __shared__ int sm[256];
    int t = threadIdx.x;
    int i = blockIdx.x * 256 + t;
    int v = (i < n) ? g_cnt[i] : 0;
    if (i < n) g_dis[i] = rsqrtf((float)v + 1.0f);
    sm[t] = v;
    __syncthreads();
    for (int off = 128; off > 0; off >>= 1) {
        if (t < off) sm[t] += sm[t + off];
        __syncthreads();
    }
    if (t == 0) g_bsum[blockIdx.x] = sm[0];
}

__global__ void scan2_kernel(int nb) {
    __shared__ int sm[1024];
    int t = threadIdx.x;
    int v = (t < nb) ? g_bsum[t] : 0;
    sm[t] = v;
    __syncthreads();
    for (int off = 1; off < 1024; off <<= 1) {
        int add = (t >= off) ? sm[t - off] : 0;
        __syncthreads();
        sm[t] += add;
        __syncthreads();
    }
    if (t < nb) g_bsum[t] = sm[t] - v;   // exclusive
}

__global__ void scan3_kernel(int n) {
    __shared__ int sm[256];
    int t = threadIdx.x;
    int i = blockIdx.x * 256 + t;
    int v = (i < n) ? g_cnt[i] : 0;
    sm[t] = v;
    __syncthreads();
    for (int off = 1; off < 256; off <<= 1) {
        int add = (t >= off) ? sm[t - off] : 0;
        __syncthreads();
        sm[t] += add;
        __syncthreads();
    }
    if (i < n) {
        int o = g_bsum[blockIdx.x] + sm[t] - v;   // exclusive
        g_off[i] = o;
        g_cur[i] = o;
    }
}

__global__ void fill_kernel(const void* __restrict__ ei, int E) {
    int i = blockIdx.x * blockDim.x + threadIdx.x;
    if (i >= E) return;
    int s = load_idx(ei, i);
    int d = load_idx(ei, (long long)E + i);
    float norm = g_dis[s] * g_dis[d];
    int pos = atomicAdd(&g_cur[d], 1);
    g_epack[pos] = make_int2(s, __float_as_int(norm));
}

// ---------------- GEMM: O[M,128] = X[M,128] @ W[128,128]^T ----------------
// R13 per ncu: keep BOTH operands in smem (R12 showed global broadcast X is
// L1-bound), get occupancy by splitting N: each CTA does a 64x64 tile.
// sW [128][68]=34.8KB + sX [64][128]=32KB = 66.8KB -> 3 CTAs/SM (24 warps
// vs R5's 16). Same proven access patterns: x = 1-cyc broadcast LDS,
// w = contiguous conflict-free LDS.64. SW_LD2=68 (mult of 4 -> aligned).
#define GEMM_TM 64
#define GEMM_TN 64
#define SW_LD2 68
__global__ __launch_bounds__(256, 3)
void gemm_kernel(const float* __restrict__ X, const float* __restrict__ W,
                 float* __restrict__ O, int M) {
    extern __shared__ float smem[];
    float* sW = smem;                    // [128][SW_LD2] (W half, transposed)
    float* sX = smem + 128 * SW_LD2;     // [64][128]

    int t = threadIdx.x;
    int row0 = blockIdx.x * GEMM_TM;
    int col0 = blockIdx.y * GEMM_TN;

    // stage W half-tile transposed: sW[k][j] = W[col0+j][k]
    for (int idx = t; idx < GEMM_TN * 128; idx += 256) {
        int j = idx >> 7, k = idx & 127;
        sW[k * SW_LD2 + j] = W[(size_t)(col0 + j) * 128 + k];
    }
    // stage X tile (float4, coalesced)
    for (int idx = t; idx < GEMM_TM * 32; idx += 256) {
        int r = idx >> 5, c = idx & 31;
        int gr = row0 + r;
        float4 v = (gr < M) ? ((const float4*)X)[(size_t)gr * 32 + c]
                            : make_float4(0.f, 0.f, 0.f, 0.f);
        ((float4*)sX)[r * 32 + c] = v;
    }
    __syncthreads();

    int wid = t >> 5, lane = t & 31;
    int j0 = lane * 2;                   // 2 cols per lane

    float acc[8][2];
    #pragma unroll
    for (int rr = 0; rr < 8; rr++) { acc[rr][0] = 0.f; acc[rr][1] = 0.f; }

    #pragma unroll 4
    for (int kk = 0; kk < 128; kk += 4) {
        // w tile: 4 float2 (8 regs), contiguous 256B per LDS -> conflict-free
        float2 w0 = *(const float2*)&sW[(kk + 0) * SW_LD2 + j0];
        float2 w1 = *(const float2*)&sW[(kk + 1) * SW_LD2 + j0];
        float2 w2 = *(const float2*)&sW[(kk + 2) * SW_LD2 + j0];
        float2 w3 = *(const float2*)&sW[(kk + 3) * SW_LD2 + j0];
        #pragma unroll
        for (int rr = 0; rr < 8; rr++) {
            float4 xv = *(const float4*)&sX[(wid * 8 + rr) * 128 + kk];
            acc[rr][0] += xv.x * w0.x + xv.y * w1.x + xv.z * w2.x + xv.w * w3.x;
            acc[rr][1] += xv.x * w0.y + xv.y * w1.y + xv.z * w2.y + xv.w * w3.y;
        }
    }

    #pragma unroll
    for (int rr = 0; rr < 8; rr++) {
        int gr = row0 + wid * 8 + rr;
        if (gr < M)
            *(float2*)&O[(size_t)gr * 128 + col0 + j0] =
                make_float2(acc[rr][0], acc[rr][1]);
    }
}

// ---------------- fused gather-aggregate + self-loop + bias + leaky ------
// One warp per dst node (proven R5 version: 2-edge unroll).
__global__ __launch_bounds__(256)
void agg_kernel(const float* __restrict__ h, const float* __restrict__ b,
                float* __restrict__ out, int n) {
    int w    = (blockIdx.x * blockDim.x + threadIdx.x) >> 5;
    int lane = threadIdx.x & 31;
    if (w >= n) return;

    int beg = g_off[w];
    int cnt = g_cnt[w];
    const float4* h4 = (const float4*)h;

    float4 acc = make_float4(0.f, 0.f, 0.f, 0.f);

    int e = 0;
    for (; e + 2 <= cnt; e += 2) {
        int2 p0 = g_epack[beg + e];
        int2 p1 = g_epack[beg + e + 1];
        float n0 = __int_as_float(p0.y);
        float n1 = __int_as_float(p1.y);
        float4 v0 = h4[(size_t)p0.x * 32 + lane];
        float4 v1 = h4[(size_t)p1.x * 32 + lane];
        acc.x += v0.x * n0 + v1.x * n1;
        acc.y += v0.y * n0 + v1.y * n1;
        acc.z += v0.z * n0 + v1.z * n1;
        acc.w += v0.w * n0 + v1.w * n1;
    }
    if (e < cnt) {
        int2 p0 = g_epack[beg + e];
        float n0 = __int_as_float(p0.y);
        float4 v0 = h4[(size_t)p0.x * 32 + lane];
        acc.x += v0.x * n0;
        acc.y += v0.y * n0;
        acc.z += v0.z * n0;
        acc.w += v0.w * n0;
    }

    float dis = g_dis[w];
    float sw  = dis * dis;
    float4 hs = h4[(size_t)w * 32 + lane];
    float4 bb = ((const float4*)b)[lane];
    acc.x += hs.x * sw + bb.x;
    acc.y += hs.y * sw + bb.y;
    acc.z += hs.z * sw + bb.z;
    acc.w += hs.w * sw + bb.w;

    acc.x = (acc.x > 0.f) ? acc.x : 0.01f * acc.x;
    acc.y = (acc.y > 0.f) ? acc.y : 0.01f * acc.y;
    acc.z = (acc.z > 0.f) ? acc.z : 0.01f * acc.z;
    acc.w = (acc.w > 0.f) ? acc.w : 0.01f * acc.w;

    ((float4*)out)[(size_t)w * 32 + lane] = acc;
}

// ---------------- launch ----------------
extern "C" void kernel_launch(void* const* d_in, const int* in_sizes, int n_in,
                              void* d_out, int out_size) {
    const float* x  = (const float*)d_in[0];
    const void*  ei = d_in[1];
    const float* W1 = (const float*)d_in[2];
    const float* b1 = (const float*)d_in[3];
    const float* W2 = (const float*)d_in[4];
    const float* b2 = (const float*)d_in[5];
    float* out = (float*)d_out;

    int n = in_sizes[0] / F;
    int E = in_sizes[1] / 2;

    void *hp_v, *x2p_v;
    cudaGetSymbolAddress(&hp_v,  g_h);
    cudaGetSymbolAddress(&x2p_v, g_x2);
    float* hp  = (float*)hp_v;
    float* x2p = (float*)x2p_v;

    const int gemm_smem = (128 * SW_LD2 + GEMM_TM * 128) * (int)sizeof(float); // 66816 B
    cudaFuncSetAttribute(gemm_kernel,
                         cudaFuncAttributeMaxDynamicSharedMemorySize, gemm_smem);

    int nb        = (n + 255) / 256;
    dim3 gemm_grid((n + GEMM_TM - 1) / GEMM_TM, 2);
    int node_grid = (n + 255) / 256;
    int edge_grid = (E + 255) / 256;
    int agg_grid  = ((long long)n * 32 + 255) / 256;

    // gemm1 has no CSR dependency; kept as the 4th launch so ncu's window
    // profiles it again next round (verifies occ/issue delta).
    zero_detect_kernel<<<node_grid, 256>>>(ei, n);       // 1
    deg_kernel<<<edge_grid, 256>>>(ei, E);               // 2
    scan1_dis_kernel<<<nb, 256>>>(n);                    // 3
    gemm_kernel<<<gemm_grid, 256, gemm_smem>>>(x, W1, hp, n);   // 4 <- profiled
    scan2_kernel<<<1, 1024>>>(nb);                       // 5
    scan3_kernel<<<nb, 256>>>(n);                        // 6
    fill_kernel<<<edge_grid, 256>>>(ei, E);              // 7

    // layer 1 aggregation (needs gemm1 + CSR)
    agg_kernel<<<agg_grid, 256>>>(hp, b1, x2p, n);

    // layer 2
    gemm_kernel<<<gemm_grid, 256, gemm_smem>>>(x2p, W2, hp, n);
    agg_kernel<<<agg_grid, 256>>>(hp, b2, out, n);
}